// round 10
// baseline (speedup 1.0000x reference)
#include <cuda_runtime.h>
#include <cuda_bf16.h>
#include <math.h>

// Problem constants (fixed by setup_inputs): B=32, N=M=1024, F=4
#define BB    32
#define NN    1024
#define MM    1024
#define LL    (NN + MM - 1)   // 2047
#define BT    256             // block threads (8 warps -> 2 per SMSP)
#define RR    4               // rows per thread (256*4 = 1024)
#define NG    (MM / 2)        // 512 column groups (2 cols per group)
#define NWARP (BT / 32)       // 8

// Epoch-skew parameters: barrier every KS steps; warp boundary gap = KS.
#define KS      8
#define WSKEW   (32 + KS - 1)                 // 39: sigma = lane + 39*warp
#define SIGMAX  (31 + WSKEW * (NWARP - 1))    // 304
#define STEPS   (NG + SIGMAX + 1)             // 816  (multiple of 8)
#define EPOCHS  (STEPS / KS)                  // 102

// Skewed move storage: rec[b][s][t] = uint2{par0 word, par1 word}; each word
// packs RR move bytes (enc = di | dj<<1) for rows 4t..4t+3 of column 2g(+1),
// where g = s - sigma(t). Coalesced 2KB per step per block.
#define SSTRIDE ((size_t)STEPS * 2048)   // per-batch bytes
__device__ __align__(16) unsigned char g_moves[(size_t)BB * SSTRIDE + 4096];
__device__ float g_loss[BB];
__device__ int   g_done;     // zero-init; self-resetting each launch

// Backtrack window: WI i-rows x WJ j-cols
#define WI 80
#define WJ 64

__device__ __forceinline__ float fsqrt_approx(float x) {
    float r;
    asm("sqrt.approx.f32 %0, %1;" : "=f"(r) : "f"(x));
    return r;
}

__global__ __launch_bounds__(BT, 1)
void dtw_fused(const float* __restrict__ preds, const float* __restrict__ targs,
               const float* __restrict__ subcoef, float* __restrict__ out)
{
    const int b    = blockIdx.x;
    const int tid  = threadIdx.x;
    const int lane = tid & 31;
    const int warp = tid >> 5;
    const int sig  = lane + WSKEW * warp;     // thread skew

    __shared__ float2 txy[MM];                            // 8 KB target basis
    __shared__ float4 sb[2][KS][NWARP];                   // epoch-buffered handoff
    __shared__ unsigned int path[LL];                     // 8 KB packed (i<<16|j)
    __shared__ __align__(16) unsigned char win[WJ * WI];  // 5 KB (i,j) moves window
    __shared__ unsigned short jt[WJ * WI];                // 10 KB jump-2 table
    __shared__ int s_i, s_j, s_cnt, s_done;
    __shared__ float warp_sums[NWARP];

    const float* pb = preds + (size_t)b * NN * 4;
    const float* tb = targs + (size_t)b * MM * 4;
    const float INF = __int_as_float(0x7f800000);

    // ---- init ----
    for (int idx = tid; idx < MM; idx += BT)
        txy[idx] = *(const float2*)(tb + (size_t)idx * 4);
    for (int idx = tid; idx < 2 * KS * NWARP; idx += BT)
        ((float4*)sb)[idx] = make_float4(INF, INF, INF, 0.0f);

    float px[RR], py[RR], left[RR];
    #pragma unroll
    for (int q = 0; q < RR; ++q) {
        const float2 pv = *(const float2*)(pb + (size_t)(tid * RR + q) * 4);
        px[q] = pv.x; py[q] = pv.y;
        left[q] = INF;
    }
    __syncthreads();

    // =====================================================================
    // Forward DP with K-deep warp skew + 1-step software-pipelined costs:
    // thread owns rows 4t..4t+3; at step s it processes column group
    // g = s - sigma (columns 2g, 2g+1), consuming costs computed during
    // step s-1 (sqrt latency fully off the DP chain).
    // In-warp handoff: 3 shfls (1-step gap). Warp boundary: gap = KS steps
    // through sb[epoch parity][s % KS][warp]; one barrier per KS steps.
    // Moves stored skewed (step-major) -> fully coalesced uint2 stores.
    // =====================================================================
    float bot0 = INF, bot1 = INF, pb1 = INF;
    unsigned char* mb = g_moves + (size_t)b * SSTRIDE + tid * 8;

    float cstc0[RR], cstc1[RR];   // costs for the CURRENT step (pipelined)
    {   // prologue: costs for step 0 (group = -sig, clamped; unused if invalid)
        const int gc = min(max(0 - sig, 0), NG - 1);
        const float2 t0 = txy[2 * gc];
        const float2 t1 = txy[2 * gc + 1];
        #pragma unroll
        for (int q = 0; q < RR; ++q) {
            const float dx0 = px[q] - t0.x, dy0 = py[q] - t0.y;
            cstc0[q] = fsqrt_approx(fmaf(dx0, dx0, dy0 * dy0));
            const float dx1 = px[q] - t1.x, dy1 = py[q] - t1.y;
            cstc1[q] = fsqrt_approx(fmaf(dx1, dx1, dy1 * dy1));
        }
    }

    for (int e = 0; e < EPOCHS; ++e) {
        const int par = e & 1;
        #pragma unroll
        for (int ks = 0; ks < KS; ++ks) {
            const int s = e * KS + ks;

            float nb0 = __shfl_up_sync(0xffffffffu, bot0, 1);
            float nb1 = __shfl_up_sync(0xffffffffu, bot1, 1);
            float nbp = __shfl_up_sync(0xffffffffu, pb1, 1);
            if (lane == 0) {
                if (warp == 0) { nb0 = INF; nb1 = INF; nbp = INF; }
                else {
                    const float4 v = sb[par ^ 1][ks][warp - 1];  // producer step s-KS
                    nb0 = v.x; nb1 = v.y; nbp = v.z;
                }
            }

            const int g = s - sig;
            if ((unsigned)g < (unsigned)NG) {
                pb1 = bot1;   // becomes "bottom at c0-1" for next step's handoff

                // ---- column c0 (costs from pipeline: cstc0) ----
                float up0 = nb0, dg0 = nbp;
                float cur0[RR];
                unsigned wa0 = 0;
                #pragma unroll
                for (int q = 0; q < RR; ++q) {
                    const float lf = left[q];
                    const float pm = fminf(dg0, lf);      // off-chain for q>0
                    float best = fminf(up0, pm);
                    if (q == 0) best = (best == INF) ? 0.0f : best;  // (0,0) seed only
                    // first-min argmin over [dg, up, lf] -> enc = di | dj<<1
                    float bm = dg0; int enc = 3;           // diag: di=1,dj=1
                    if (up0 < bm) { bm = up0; enc = 1; }   // up:   di=1,dj=0
                    if (lf  < bm) { enc = 2; }             // left: di=0,dj=1
                    const float cur = best + cstc0[q];
                    dg0 = lf;
                    up0 = cur;
                    cur0[q] = cur;
                    wa0 |= (unsigned)enc << (8 * q);
                }

                // ---- column c0+1 (costs from pipeline: cstc1) ----
                float up1 = nb1, dg1 = nb0;
                unsigned wb0 = 0;
                #pragma unroll
                for (int q = 0; q < RR; ++q) {
                    const float lf = cur0[q];
                    const float pm = fminf(dg1, lf);
                    const float best = fminf(up1, pm);
                    float bm = dg1; int enc = 3;
                    if (up1 < bm) { bm = up1; enc = 1; }
                    if (lf  < bm) { enc = 2; }
                    const float cur = best + cstc1[q];
                    dg1 = lf;
                    up1 = cur;
                    left[q] = cur;                         // left for next group
                    wb0 |= (unsigned)enc << (8 * q);
                }

                bot0 = cur0[RR - 1];
                bot1 = left[RR - 1];

                *(uint2*)(mb + (size_t)s * 2048) = make_uint2(wa0, wb0);  // coalesced
            }

            if (lane == 31)
                sb[par][ks][warp] = make_float4(bot0, bot1, pb1, 0.0f);

            // ---- pipeline: compute costs for step s+1 (group g+1, clamped) ----
            {
                const int gn = min(max(s + 1 - sig, 0), NG - 1);
                const float2 t0 = txy[2 * gn];
                const float2 t1 = txy[2 * gn + 1];
                #pragma unroll
                for (int q = 0; q < RR; ++q) {
                    const float dx0 = px[q] - t0.x, dy0 = py[q] - t0.y;
                    cstc0[q] = fsqrt_approx(fmaf(dx0, dx0, dy0 * dy0));
                    const float dx1 = px[q] - t1.x, dy1 = py[q] - t1.y;
                    cstc1[q] = fsqrt_approx(fmaf(dx1, dx1, dy1 * dy1));
                }
            }
        }
        __syncthreads();
    }

    // =====================================================================
    // Backtrack: block-cooperative 80x64 (i,j) windows gathered from the
    // skewed storage, + jump-2 table. jt entry (uint16): [7:0]=a-delta of
    // 2 steps, [8]=di1, [9]=dj1, [11:10]=di_tot, [13:12]=dj_tot, [14]=v2.
    // Thread 0 walks 2 path steps per dependent shared load.
    // =====================================================================
    if (tid == 0) {
        s_i = NN - 1; s_j = MM - 1; s_cnt = 1; s_done = 0;
        path[0] = ((unsigned)(NN - 1) << 16) | (unsigned)(MM - 1);
    }
    const unsigned char* mvb = g_moves + (size_t)b * SSTRIDE;
    __syncthreads();

    for (;;) {
        if (s_done) break;
        const int ci  = s_i, cj = s_j;
        const int ilo = max(ci - 76, 0) & ~3;   // 4-aligned; io start in [76,79] (or ci)
        const int jlo = max(cj - 62, 0) & ~1;   // even;      jo start in [62,63] (or cj)
        const int t0b = ilo >> 2;               // first t-group
        const int g0b = jlo >> 1;               // first column-pair

        // gather window: 32 column-pairs x 20 t-groups = 640 uint2 loads.
        // word.x -> column jlo+2jp, word.y -> column jlo+2jp+1, rows 4t..4t+3.
        // s(t, g) = g + (t&31) + WSKEW*(t>>5).
        for (int task = tid; task < 32 * 20; task += BT) {
            const int jp = task / 20;
            const int tg = task % 20;
            const int tt = min(t0b + tg, BT - 1);          // clamp: rows i>=1024 never visited
            const int ss = g0b + jp + (tt & 31) + WSKEW * (tt >> 5);
            const uint2 v = *(const uint2*)(mvb + (size_t)ss * 2048 + tt * 8);
            *(unsigned*)&win[(2 * jp)     * WI + tg * 4] = v.x;
            *(unsigned*)&win[(2 * jp + 1) * WI + tg * 4] = v.y;
        }
        __syncthreads();

        // build jump-2 table: thread = (col jo = tid>>2, io segment of 20)
        {
            const int jo  = tid >> 2;
            const int io0 = (tid & 3) * 20;
            int a = jo * WI + io0;
            #pragma unroll 4
            for (int io = io0; io < io0 + 20; ++io, ++a) {
                const int m1  = win[a] & 3;
                const int di1 = m1 & 1;
                const int dj1 = (m1 >> 1) & 1;
                const int io2 = io - di1;
                const int jo2 = jo - dj1;
                const int v2  = ((io2 | jo2) >= 0) ? 1 : 0;
                const int m2  = v2 ? (win[a - di1 - dj1 * WI] & 3) : 0;
                const int dit = di1 + (m2 & 1);
                const int djt = dj1 + ((m2 >> 1) & 1);
                const int ad  = dit + djt * WI;
                jt[a] = (unsigned short)(ad | (di1 << 8) | (dj1 << 9)
                                            | (dit << 10) | (djt << 12) | (v2 << 14));
            }
        }
        __syncthreads();

        if (tid == 0) {
            int i = ci, j = cj, cnt = s_cnt, done = 0;
            int io = i - ilo, jo = j - jlo;
            int a = jo * WI + io;
            for (;;) {
                const unsigned w = jt[a];
                const int di1 = (w >> 8) & 1;
                const int dj1 = (w >> 9) & 1;
                const int i1 = i - di1, j1 = j - dj1;
                path[cnt++] = ((unsigned)i1 << 16) | (unsigned)j1;
                if ((i1 | j1) == 0) { i = i1; j = j1; done = 1; break; }
                if (!((w >> 14) & 1)) { i = i1; j = j1; break; }  // step2 leaves window
                const int dit = (w >> 10) & 3;
                const int djt = (w >> 12) & 3;
                i -= dit; j -= djt;
                path[cnt++] = ((unsigned)i << 16) | (unsigned)j;
                if ((i | j) == 0) { done = 1; break; }
                io -= dit; jo -= djt;
                a  -= (int)(w & 0xFFu);
                if ((io | jo) < 0) break;                          // left window
            }
            s_i = i; s_j = j; s_cnt = cnt; s_done = done;
        }
        __syncthreads();
    }

    // ---- path loss ----
    const float c0s = subcoef[0];
    const float c1s = subcoef[1];
    const int  len = s_cnt;

    float acc = 0.0f;
    for (int p = tid; p < len; p += BT) {
        const unsigned pk = path[p];
        const int ai = (int)(pk >> 16);
        const int bj = (int)(pk & 0xffffu);
        const float2 pp = *(const float2*)(pb + (size_t)ai * 4);
        const float2 tv = *(const float2*)(tb + (size_t)bj * 4);
        acc += fabsf(pp.x - tv.x) * c0s + fabsf(pp.y - tv.y) * c1s;
    }
    #pragma unroll
    for (int off = 16; off > 0; off >>= 1)
        acc += __shfl_down_sync(0xffffffffu, acc, off);
    if (lane == 0) warp_sums[warp] = acc;
    __syncthreads();

    // ---- last-CTA deterministic finalize (fixed-order sum) ----
    if (tid == 0) {
        float tot = 0.0f;
        #pragma unroll
        for (int w = 0; w < NWARP; ++w) tot += warp_sums[w];
        g_loss[b] = tot;
        __threadfence();
        const int old = atomicAdd(&g_done, 1);
        if (old == BB - 1) {
            __threadfence();
            float t2 = 0.0f;
            #pragma unroll
            for (int x = 0; x < BB; ++x) t2 += g_loss[x];
            out[0] = t2;
            g_done = 0;   // self-reset for next graph replay
        }
    }
}

extern "C" void kernel_launch(void* const* d_in, const int* in_sizes, int n_in,
                              void* d_out, int out_size)
{
    const float* preds   = (const float*)d_in[0];
    const float* targs   = (const float*)d_in[1];
    const float* subcoef = (const float*)d_in[2];
    float* out = (float*)d_out;

    dtw_fused<<<BB, BT>>>(preds, targs, subcoef, out);
}

// round 11
// speedup vs baseline: 1.1841x; 1.1841x over previous
#include <cuda_runtime.h>
#include <cuda_bf16.h>
#include <math.h>

// Problem constants (fixed by setup_inputs): B=32, N=M=1024, F=4
#define BB    32
#define NN    1024
#define MM    1024
#define BT    256             // block threads (8 warps -> 2 per SMSP)
#define RR    4               // rows per thread (256*4 = 1024)
#define NG    (MM / 2)        // 512 column groups (2 cols per group)
#define NWARP (BT / 32)       // 8

// Epoch-skew parameters: barrier every KS steps; warp boundary gap = KS.
#define KS      8
#define WSKEW   (32 + KS - 1)                 // 39: sigma = lane + 39*warp
#define SIGMAX  (31 + WSKEW * (NWARP - 1))    // 304
#define STEPS   (NG + SIGMAX)                 // 816 (multiple of 8; last cell at s=815)
#define EPOCHS  (STEPS / KS)                  // 102

__device__ float g_loss[BB];
__device__ int   g_done;     // zero-init; self-resetting each launch

__device__ __forceinline__ float fsqrt_approx(float x) {
    float r;
    asm("sqrt.approx.f32 %0, %1;" : "=f"(r) : "f"(x));
    return r;
}

__global__ __launch_bounds__(BT, 1)
void dtw_fused(const float* __restrict__ preds, const float* __restrict__ targs,
               const float* __restrict__ subcoef, float* __restrict__ out)
{
    const int b    = blockIdx.x;
    const int tid  = threadIdx.x;
    const int lane = tid & 31;
    const int warp = tid >> 5;
    const int sig  = lane + WSKEW * warp;     // thread skew

    __shared__ float2 txy[MM];                // 8 KB target basis
    __shared__ float4 sbD[2][KS][NWARP];      // D handoff: {bot0, bot1, pb1}
    __shared__ float4 sbA[2][KS][NWARP];      // A handoff: {Ab0,  Ab1,  Apb}

    const float* pb = preds + (size_t)b * NN * 4;
    const float* tb = targs + (size_t)b * MM * 4;
    const float INF = __int_as_float(0x7f800000);
    const float c0s = subcoef[0];
    const float c1s = subcoef[1];

    // ---- init ----
    for (int idx = tid; idx < MM; idx += BT)
        txy[idx] = *(const float2*)(tb + (size_t)idx * 4);
    for (int idx = tid; idx < 2 * KS * NWARP; idx += BT) {
        ((float4*)sbD)[idx] = make_float4(INF, INF, INF, 0.0f);
        ((float4*)sbA)[idx] = make_float4(0.0f, 0.0f, 0.0f, 0.0f);
    }

    float px[RR], py[RR], left[RR], Aleft[RR];
    #pragma unroll
    for (int q = 0; q < RR; ++q) {
        const float2 pv = *(const float2*)(pb + (size_t)(tid * RR + q) * 4);
        px[q] = pv.x; py[q] = pv.y;
        left[q]  = INF;
        Aleft[q] = 0.0f;
    }
    __syncthreads();

    // =====================================================================
    // Forward DP with loss propagation: thread owns rows 4t..4t+3; at step s
    // it processes column group g = s - sigma (columns 2g, 2g+1), carrying
    //   D[i,j] = cost(i,j) + min(D[i-1,j-1], D[i-1,j], D[i,j-1])
    //   A[i,j] = A[argmin parent] + |dx|*c0 + |dy|*c1   (path loss so far)
    // Parent selection: first-min equality order [diag, up, left] = jnp.argmin.
    // In-warp handoff: 6 shfls (1-step gap). Warp boundary: gap = KS steps
    // through sb[epoch parity][s % KS][warp]; one barrier per KS steps.
    // Answer per batch = A at (NN-1, MM-1), produced by thread BT-1 at the
    // final step. No move matrix, no backtrack, no gmem traffic.
    // =====================================================================
    float bot0 = INF, bot1 = INF, pb1 = INF;
    float Ab0  = 0.0f, Ab1 = 0.0f, Apb = 0.0f;

    float cst0[RR], cst1[RR], lc0[RR], lc1[RR];   // pipelined cost & loss terms
    {   // prologue: terms for step 0 (group = -sig, clamped; unused if invalid)
        const int gc = min(max(0 - sig, 0), NG - 1);
        const float2 t0 = txy[2 * gc];
        const float2 t1 = txy[2 * gc + 1];
        #pragma unroll
        for (int q = 0; q < RR; ++q) {
            const float dx0 = px[q] - t0.x, dy0 = py[q] - t0.y;
            cst0[q] = fsqrt_approx(fmaf(dx0, dx0, dy0 * dy0));
            lc0[q]  = fmaf(fabsf(dy0), c1s, fabsf(dx0) * c0s);
            const float dx1 = px[q] - t1.x, dy1 = py[q] - t1.y;
            cst1[q] = fsqrt_approx(fmaf(dx1, dx1, dy1 * dy1));
            lc1[q]  = fmaf(fabsf(dy1), c1s, fabsf(dx1) * c0s);
        }
    }

    for (int e = 0; e < EPOCHS; ++e) {
        const int par = e & 1;
        #pragma unroll
        for (int ks = 0; ks < KS; ++ks) {
            const int s = e * KS + ks;

            float nb0 = __shfl_up_sync(0xffffffffu, bot0, 1);
            float nb1 = __shfl_up_sync(0xffffffffu, bot1, 1);
            float nbp = __shfl_up_sync(0xffffffffu, pb1, 1);
            float na0 = __shfl_up_sync(0xffffffffu, Ab0, 1);
            float na1 = __shfl_up_sync(0xffffffffu, Ab1, 1);
            float nap = __shfl_up_sync(0xffffffffu, Apb, 1);
            if (lane == 0) {
                if (warp == 0) {
                    nb0 = INF; nb1 = INF; nbp = INF;
                    na0 = 0.0f; na1 = 0.0f; nap = 0.0f;
                } else {
                    const float4 vD = sbD[par ^ 1][ks][warp - 1];  // producer step s-KS
                    nb0 = vD.x; nb1 = vD.y; nbp = vD.z;
                    const float4 vA = sbA[par ^ 1][ks][warp - 1];
                    na0 = vA.x; na1 = vA.y; nap = vA.z;
                }
            }

            const int g = s - sig;
            if ((unsigned)g < (unsigned)NG) {
                pb1 = bot1;   // bottom at c0-1 for next step's handoff
                Apb = Ab1;

                // ---- column c0 ----
                float up = nb0, dg = nbp, Aup = na0, Adg = nap;
                float cur0[RR], Acur0[RR];
                #pragma unroll
                for (int q = 0; q < RR; ++q) {
                    const float lf  = left[q];
                    const float Alf = Aleft[q];
                    const float pm  = fminf(dg, lf);
                    float best = fminf(up, pm);
                    // first-min parent select [diag, up, left] (= jnp.argmin order)
                    const bool p0 = (best == dg);
                    const bool p1 = (best == up);
                    const float Asel = p0 ? Adg : (p1 ? Aup : Alf);
                    if (q == 0) best = (best == INF) ? 0.0f : best;  // (0,0) seed only
                    const float cur  = best + cst0[q];
                    const float Acur = Asel + lc0[q];
                    dg = lf;  Adg = Alf;
                    up = cur; Aup = Acur;
                    cur0[q] = cur; Acur0[q] = Acur;
                }

                // ---- column c0+1 ----
                up = nb1; dg = nb0; Aup = na1; Adg = na0;
                #pragma unroll
                for (int q = 0; q < RR; ++q) {
                    const float lf  = cur0[q];
                    const float Alf = Acur0[q];
                    const float pm  = fminf(dg, lf);
                    const float best = fminf(up, pm);
                    const bool p0 = (best == dg);
                    const bool p1 = (best == up);
                    const float Asel = p0 ? Adg : (p1 ? Aup : Alf);
                    const float cur  = best + cst1[q];
                    const float Acur = Asel + lc1[q];
                    dg = lf;  Adg = Alf;
                    up = cur; Aup = Acur;
                    left[q] = cur; Aleft[q] = Acur;
                }

                bot0 = cur0[RR - 1];  Ab0 = Acur0[RR - 1];
                bot1 = left[RR - 1];  Ab1 = Aleft[RR - 1];
            }

            if (lane == 31) {
                sbD[par][ks][warp] = make_float4(bot0, bot1, pb1, 0.0f);
                sbA[par][ks][warp] = make_float4(Ab0,  Ab1,  Apb, 0.0f);
            }

            // ---- pipeline: cost & loss terms for step s+1 (clamped group) ----
            {
                const int gn = min(max(s + 1 - sig, 0), NG - 1);
                const float2 t0 = txy[2 * gn];
                const float2 t1 = txy[2 * gn + 1];
                #pragma unroll
                for (int q = 0; q < RR; ++q) {
                    const float dx0 = px[q] - t0.x, dy0 = py[q] - t0.y;
                    cst0[q] = fsqrt_approx(fmaf(dx0, dx0, dy0 * dy0));
                    lc0[q]  = fmaf(fabsf(dy0), c1s, fabsf(dx0) * c0s);
                    const float dx1 = px[q] - t1.x, dy1 = py[q] - t1.y;
                    cst1[q] = fsqrt_approx(fmaf(dx1, dx1, dy1 * dy1));
                    lc1[q]  = fmaf(fabsf(dy1), c1s, fabsf(dx1) * c0s);
                }
            }
        }
        __syncthreads();
    }

    // ---- result: thread BT-1's Ab1 is A at (NN-1, MM-1) ----
    if (tid == BT - 1) {
        g_loss[b] = Ab1;
        __threadfence();
        const int old = atomicAdd(&g_done, 1);
        if (old == BB - 1) {
            __threadfence();
            float t2 = 0.0f;
            #pragma unroll
            for (int x = 0; x < BB; ++x) t2 += g_loss[x];
            out[0] = t2;
            g_done = 0;   // self-reset for next graph replay
        }
    }
}

extern "C" void kernel_launch(void* const* d_in, const int* in_sizes, int n_in,
                              void* d_out, int out_size)
{
    const float* preds   = (const float*)d_in[0];
    const float* targs   = (const float*)d_in[1];
    const float* subcoef = (const float*)d_in[2];
    float* out = (float*)d_out;

    dtw_fused<<<BB, BT>>>(preds, targs, subcoef, out);
}